// round 4
// baseline (speedup 1.0000x reference)
#include <cuda_runtime.h>
#include <cuda_bf16.h>

// Shapes
#define B_DIM 2048
#define N_Z 8
#define NOISE 32
#define STATE 1024
#define HID 1024
#define EPI_H 512
#define PRIOR_H 5
#define PRI_N 160   // 32 ensembles * 5

typedef unsigned long long u64;

// ---- f32x2 packed helpers (FFMA2 path, ptxas never emits from C++) ----
__device__ __forceinline__ u64 pk2(float lo, float hi) {
    u64 r; asm("mov.b64 %0,{%1,%2};" : "=l"(r) : "f"(lo), "f"(hi)); return r;
}
__device__ __forceinline__ u64 fma2(u64 a, u64 b, u64 c) {
    u64 d; asm("fma.rn.f32x2 %0,%1,%2,%3;" : "=l"(d) : "l"(a), "l"(b), "l"(c)); return d;
}
__device__ __forceinline__ float2 unpk(u64 v) {
    float2 r; asm("mov.b64 {%0,%1},%2;" : "=f"(r.x), "=f"(r.y) : "l"(v)); return r;
}

// Scratch (no allocation allowed)
__device__ float g_H[B_DIM * EPI_H];     // xf @ Wep1[0:2048] + bep1 (pre-relu)
__device__ float g_P1[B_DIM * PRI_N];    // relu(x @ Wp1 + bp1)
__device__ float g_W1r[STATE * PRI_N];   // repacked prior weight [k][e*5+h]

// ---------------------------------------------------------------------------
// Repack Wp1[32][1024][5] -> W1r[1024][160]
// ---------------------------------------------------------------------------
__global__ void repack_wp1(const float* __restrict__ Wp1) {
    int idx = blockIdx.x * 256 + threadIdx.x;
    if (idx < STATE * PRI_N) {
        int k = idx / PRI_N;
        int c = idx - k * PRI_N;
        int e = c / PRIOR_H;
        int h = c - e * PRIOR_H;
        g_W1r[idx] = Wp1[e * (STATE * PRIOR_H) + k * PRIOR_H + h];
    }
}

// ---------------------------------------------------------------------------
// GEMM1: g_H[2048][512] = [x|feature] @ Wep1[0:2048] + bep1   (no relu)
// BM=128 BN=64 BK=16, 256 threads, 8x4 register tile (row-paired f32x2)
// ---------------------------------------------------------------------------
#define E_BM 128
#define E_BN 64
#define E_BK 16
__global__ __launch_bounds__(256) void sgemm_epi(
    const float* __restrict__ X, const float* __restrict__ F,
    const float* __restrict__ W, const float* __restrict__ bias) {
    __shared__ float As[2][E_BK][E_BM + 4];
    __shared__ float Bs[2][E_BK][E_BN];

    const int tid = threadIdx.x;
    const int row0 = blockIdx.y * E_BM;
    const int col0 = blockIdx.x * E_BN;

    const int ar = tid >> 2;          // 0..63
    const int ac4 = tid & 3;          // 0..3  (k group of 4)
    const int bkr = tid >> 4;         // 0..15
    const int bjc = tid & 15;         // 0..15 (j group of 4)
    const int ty = tid >> 4;          // 0..15 -> rows ty*8..+7
    const int tx = tid & 15;          // 0..15 -> cols tx*4..+3

    u64 acc2[4][4];   // row-pair (2*i2, 2*i2+1) x col j
#pragma unroll
    for (int i = 0; i < 4; i++)
#pragma unroll
        for (int j = 0; j < 4; j++) acc2[i][j] = 0ULL;

    float4 pa0, pa1, pb;

    // prefetch tile 0
    {
        int k = ac4 * 4;
        pa0 = *(const float4*)(X + (row0 + ar) * 1024 + k);
        pa1 = *(const float4*)(X + (row0 + ar + 64) * 1024 + k);
        pb  = *(const float4*)(W + bkr * EPI_H + col0 + bjc * 4);
    }
    {
        As[0][ac4 * 4 + 0][ar] = pa0.x; As[0][ac4 * 4 + 1][ar] = pa0.y;
        As[0][ac4 * 4 + 2][ar] = pa0.z; As[0][ac4 * 4 + 3][ar] = pa0.w;
        As[0][ac4 * 4 + 0][ar + 64] = pa1.x; As[0][ac4 * 4 + 1][ar + 64] = pa1.y;
        As[0][ac4 * 4 + 2][ar + 64] = pa1.z; As[0][ac4 * 4 + 3][ar + 64] = pa1.w;
        *(float4*)&Bs[0][bkr][bjc * 4] = pb;
    }
    __syncthreads();

    const int NT = 2048 / E_BK;  // 128
    int buf = 0;
    for (int kt = 0; kt < NT; kt++) {
        if (kt + 1 < NT) {
            int kg = (kt + 1) * E_BK + ac4 * 4;
            const float* src = (kg < 1024) ? X : F;
            int kk = kg & 1023;
            pa0 = *(const float4*)(src + (row0 + ar) * 1024 + kk);
            pa1 = *(const float4*)(src + (row0 + ar + 64) * 1024 + kk);
            pb  = *(const float4*)(W + ((kt + 1) * E_BK + bkr) * EPI_H + col0 + bjc * 4);
        }
#pragma unroll
        for (int kk = 0; kk < E_BK; kk++) {
            ulonglong2 a01 = *(const ulonglong2*)&As[buf][kk][ty * 8];
            ulonglong2 a23 = *(const ulonglong2*)&As[buf][kk][ty * 8 + 4];
            float4 rb = *(const float4*)&Bs[buf][kk][tx * 4];
            u64 a2[4] = {a01.x, a01.y, a23.x, a23.y};
            u64 bd[4];
            bd[0] = pk2(rb.x, rb.x); bd[1] = pk2(rb.y, rb.y);
            bd[2] = pk2(rb.z, rb.z); bd[3] = pk2(rb.w, rb.w);
#pragma unroll
            for (int i = 0; i < 4; i++)
#pragma unroll
                for (int j = 0; j < 4; j++)
                    acc2[i][j] = fma2(a2[i], bd[j], acc2[i][j]);
        }
        if (kt + 1 < NT) {
            int nb = buf ^ 1;
            As[nb][ac4 * 4 + 0][ar] = pa0.x; As[nb][ac4 * 4 + 1][ar] = pa0.y;
            As[nb][ac4 * 4 + 2][ar] = pa0.z; As[nb][ac4 * 4 + 3][ar] = pa0.w;
            As[nb][ac4 * 4 + 0][ar + 64] = pa1.x; As[nb][ac4 * 4 + 1][ar + 64] = pa1.y;
            As[nb][ac4 * 4 + 2][ar + 64] = pa1.z; As[nb][ac4 * 4 + 3][ar + 64] = pa1.w;
            *(float4*)&Bs[nb][bkr][bjc * 4] = pb;
        }
        __syncthreads();
        buf ^= 1;
    }

    float4 bv = *(const float4*)(bias + col0 + tx * 4);
#pragma unroll
    for (int i2 = 0; i2 < 4; i2++) {
        float2 u0 = unpk(acc2[i2][0]), u1 = unpk(acc2[i2][1]);
        float2 u2 = unpk(acc2[i2][2]), u3 = unpk(acc2[i2][3]);
        int r = row0 + ty * 8 + 2 * i2;
        float4 olo, ohi;
        olo.x = u0.x + bv.x; olo.y = u1.x + bv.y; olo.z = u2.x + bv.z; olo.w = u3.x + bv.w;
        ohi.x = u0.y + bv.x; ohi.y = u1.y + bv.y; ohi.z = u2.y + bv.z; ohi.w = u3.y + bv.w;
        *(float4*)(g_H + r * EPI_H + col0 + tx * 4) = olo;
        *(float4*)(g_H + (r + 1) * EPI_H + col0 + tx * 4) = ohi;
    }
}

// ---------------------------------------------------------------------------
// Prior GEMM: g_P1[2048][160] = relu(x @ g_W1r + bp1)   (f32x2)
// ---------------------------------------------------------------------------
#define P_BM 64
#define P_BN 32
#define P_BK 16
__global__ __launch_bounds__(128) void sgemm_prior(
    const float* __restrict__ X, const float* __restrict__ bp1) {
    __shared__ float As[2][P_BK][P_BM + 4];
    __shared__ float Bs[2][P_BK][P_BN];

    const int tid = threadIdx.x;
    const int row0 = blockIdx.y * P_BM;
    const int col0 = blockIdx.x * P_BN;

    const int ar = tid >> 2;      // 0..31
    const int ac4 = tid & 3;
    const int bkr = tid >> 3;     // 0..15
    const int bjc = tid & 7;      // 0..7
    const int ty = tid >> 3;      // 0..15 -> rows ty*4
    const int tx = tid & 7;       // 0..7  -> cols tx*4

    u64 acc2[2][4];
#pragma unroll
    for (int i = 0; i < 2; i++)
#pragma unroll
        for (int j = 0; j < 4; j++) acc2[i][j] = 0ULL;

    float4 pa0, pa1, pb;
    {
        int k = ac4 * 4;
        pa0 = *(const float4*)(X + (row0 + ar) * STATE + k);
        pa1 = *(const float4*)(X + (row0 + ar + 32) * STATE + k);
        pb  = *(const float4*)(g_W1r + bkr * PRI_N + col0 + bjc * 4);
    }
    {
        As[0][ac4 * 4 + 0][ar] = pa0.x; As[0][ac4 * 4 + 1][ar] = pa0.y;
        As[0][ac4 * 4 + 2][ar] = pa0.z; As[0][ac4 * 4 + 3][ar] = pa0.w;
        As[0][ac4 * 4 + 0][ar + 32] = pa1.x; As[0][ac4 * 4 + 1][ar + 32] = pa1.y;
        As[0][ac4 * 4 + 2][ar + 32] = pa1.z; As[0][ac4 * 4 + 3][ar + 32] = pa1.w;
        *(float4*)&Bs[0][bkr][bjc * 4] = pb;
    }
    __syncthreads();

    const int NT = STATE / P_BK;  // 64
    int buf = 0;
    for (int kt = 0; kt < NT; kt++) {
        if (kt + 1 < NT) {
            int kg = (kt + 1) * P_BK + ac4 * 4;
            pa0 = *(const float4*)(X + (row0 + ar) * STATE + kg);
            pa1 = *(const float4*)(X + (row0 + ar + 32) * STATE + kg);
            pb  = *(const float4*)(g_W1r + ((kt + 1) * P_BK + bkr) * PRI_N + col0 + bjc * 4);
        }
#pragma unroll
        for (int kk = 0; kk < P_BK; kk++) {
            ulonglong2 aa = *(const ulonglong2*)&As[buf][kk][ty * 4];
            float4 rb = *(const float4*)&Bs[buf][kk][tx * 4];
            u64 a2[2] = {aa.x, aa.y};
            u64 bd[4];
            bd[0] = pk2(rb.x, rb.x); bd[1] = pk2(rb.y, rb.y);
            bd[2] = pk2(rb.z, rb.z); bd[3] = pk2(rb.w, rb.w);
#pragma unroll
            for (int i = 0; i < 2; i++)
#pragma unroll
                for (int j = 0; j < 4; j++)
                    acc2[i][j] = fma2(a2[i], bd[j], acc2[i][j]);
        }
        if (kt + 1 < NT) {
            int nb = buf ^ 1;
            As[nb][ac4 * 4 + 0][ar] = pa0.x; As[nb][ac4 * 4 + 1][ar] = pa0.y;
            As[nb][ac4 * 4 + 2][ar] = pa0.z; As[nb][ac4 * 4 + 3][ar] = pa0.w;
            As[nb][ac4 * 4 + 0][ar + 32] = pa1.x; As[nb][ac4 * 4 + 1][ar + 32] = pa1.y;
            As[nb][ac4 * 4 + 2][ar + 32] = pa1.z; As[nb][ac4 * 4 + 3][ar + 32] = pa1.w;
            *(float4*)&Bs[nb][bkr][bjc * 4] = pb;
        }
        __syncthreads();
        buf ^= 1;
    }

    float4 bv = *(const float4*)(bp1 + col0 + tx * 4);
#pragma unroll
    for (int i2 = 0; i2 < 2; i2++) {
        float2 u0 = unpk(acc2[i2][0]), u1 = unpk(acc2[i2][1]);
        float2 u2 = unpk(acc2[i2][2]), u3 = unpk(acc2[i2][3]);
        int r = row0 + ty * 4 + 2 * i2;
        float4 olo, ohi;
        olo.x = fmaxf(u0.x + bv.x, 0.f); olo.y = fmaxf(u1.x + bv.y, 0.f);
        olo.z = fmaxf(u2.x + bv.z, 0.f); olo.w = fmaxf(u3.x + bv.w, 0.f);
        ohi.x = fmaxf(u0.y + bv.x, 0.f); ohi.y = fmaxf(u1.y + bv.y, 0.f);
        ohi.z = fmaxf(u2.y + bv.z, 0.f); ohi.w = fmaxf(u3.y + bv.w, 0.f);
        *(float4*)(g_P1 + r * PRI_N + col0 + tx * 4) = olo;
        *(float4*)(g_P1 + (r + 1) * PRI_N + col0 + tx * 4) = ohi;
    }
}

// ---------------------------------------------------------------------------
// Fused epilogue (persistent, f32x2): per (b,n):
//   out = sum_j relu(H[b][j] + z.W1z[:,j]) * (Wep2[j,:].z) + sum_e (p[b,e]+bep2[e]) z[e]
// One f32x2 accumulator carries (hz, wz) simultaneously; z pre-duplicated in
// shared so the inner loop is pure LDS.128 + FMA2.
// ---------------------------------------------------------------------------
#define EPI_GRID 152
__global__ __launch_bounds__(512, 1) void epilogue_kernel(
    const float* __restrict__ Z, const float* __restrict__ Wep1,
    const float* __restrict__ Wep2, const float* __restrict__ bep2,
    const float* __restrict__ Wp2, const float* __restrict__ bp2,
    const float* __restrict__ Wp3, const float* __restrict__ bp3,
    float* __restrict__ out) {
    __shared__ __align__(16) float2 sZd[N_Z * NOISE];  // (z,z) dup, [n][k]
    __shared__ float sP[NOISE];                        // prior p[e] + bep2[e]
    __shared__ float sRed[16][N_Z];

    const int tid = threadIdx.x;
    const int j = tid;           // 0..511
    const int lane = tid & 31;
    const int warp = tid >> 5;

    // register-resident packed weights: wpair[k] = (W1z[k][j], Wep2[j][k])
    u64 wpair[NOISE];
#pragma unroll
    for (int k = 0; k < NOISE; k++) {
        float w1 = Wep1[(2048 + k) * EPI_H + j];
        float w2 = Wep2[j * NOISE + k];
        wpair[k] = pk2(w1, w2);
    }

    for (int b = blockIdx.x; b < B_DIM; b += EPI_GRID) {
        const float Hj = g_H[b * EPI_H + j];

        if (tid < 256) {
            // z loaders (warps 0-7): duplicate into shared
            float v = Z[b * (N_Z * NOISE) + tid];
            sZd[tid] = make_float2(v, v);
        } else if (tid < 288) {
            // prior MLP for ensemble member e (warp 8)
            int e = tid - 256;
            const float* p1 = g_P1 + b * PRI_N + e * PRIOR_H;
            float h1[PRIOR_H];
#pragma unroll
            for (int h = 0; h < PRIOR_H; h++) h1[h] = p1[h];
            float h2[PRIOR_H];
#pragma unroll
            for (int g = 0; g < PRIOR_H; g++) {
                float s = bp2[e * PRIOR_H + g];
#pragma unroll
                for (int h = 0; h < PRIOR_H; h++)
                    s = fmaf(h1[h], Wp2[e * 25 + h * PRIOR_H + g], s);
                h2[g] = fmaxf(s, 0.f);
            }
            float p = bp3[e];
#pragma unroll
            for (int g = 0; g < PRIOR_H; g++)
                p = fmaf(h2[g], Wp3[e * PRIOR_H + g], p);
            sP[e] = p + bep2[e];
        }
        __syncthreads();

        float part[N_Z];
#pragma unroll
        for (int n = 0; n < N_Z; n++) {
            const ulonglong2* zp = (const ulonglong2*)(sZd + n * NOISE);
            u64 acc = 0ULL;   // (hz, wz)
#pragma unroll
            for (int k2 = 0; k2 < NOISE / 2; k2++) {
                ulonglong2 zz = zp[k2];           // dup pairs for k=2k2, 2k2+1
                acc = fma2(zz.x, wpair[2 * k2], acc);
                acc = fma2(zz.y, wpair[2 * k2 + 1], acc);
            }
            float2 u = unpk(acc);                 // u.x = hz, u.y = wz
            part[n] = fmaxf(Hj + u.x, 0.f) * u.y;
        }

        // reduce over 512 threads
#pragma unroll
        for (int n = 0; n < N_Z; n++) {
            float v = part[n];
            v += __shfl_xor_sync(0xffffffffu, v, 16);
            v += __shfl_xor_sync(0xffffffffu, v, 8);
            v += __shfl_xor_sync(0xffffffffu, v, 4);
            v += __shfl_xor_sync(0xffffffffu, v, 2);
            v += __shfl_xor_sync(0xffffffffu, v, 1);
            if (lane == 0) sRed[warp][n] = v;
        }
        __syncthreads();

        if (tid < N_Z) {
            float s = 0.f;
#pragma unroll
            for (int w = 0; w < 16; w++) s += sRed[w][tid];
#pragma unroll
            for (int e = 0; e < NOISE; e++)
                s = fmaf(sP[e], sZd[tid * NOISE + e].x, s);
            out[b * N_Z + tid] = s;
        }
        __syncthreads();
    }
}

// ---------------------------------------------------------------------------
extern "C" void kernel_launch(void* const* d_in, const int* in_sizes, int n_in,
                              void* d_out, int out_size) {
    const float* x    = (const float*)d_in[0];
    const float* feat = (const float*)d_in[1];
    const float* z    = (const float*)d_in[2];
    const float* Wep1 = (const float*)d_in[3];
    const float* bep1 = (const float*)d_in[4];
    const float* Wep2 = (const float*)d_in[5];
    const float* bep2 = (const float*)d_in[6];
    const float* Wp1  = (const float*)d_in[7];
    const float* bp1  = (const float*)d_in[8];
    const float* Wp2  = (const float*)d_in[9];
    const float* bp2  = (const float*)d_in[10];
    const float* Wp3  = (const float*)d_in[11];
    const float* bp3  = (const float*)d_in[12];
    float* out = (float*)d_out;

    repack_wp1<<<(STATE * PRI_N + 255) / 256, 256>>>(Wp1);
    sgemm_epi<<<dim3(EPI_H / E_BN, B_DIM / E_BM), 256>>>(x, feat, Wep1, bep1);
    sgemm_prior<<<dim3(PRI_N / P_BN, B_DIM / P_BM), 128>>>(x, bp1);
    epilogue_kernel<<<EPI_GRID, 512>>>(z, Wep1, Wep2, bep2, Wp2, bp2, Wp3, bp3, out);
}

// round 6
// speedup vs baseline: 1.4240x; 1.4240x over previous
#include <cuda_runtime.h>
#include <cuda_bf16.h>
#include <cstdint>

// Shapes
#define B_DIM 2048
#define N_Z 8
#define NOISE 32
#define STATE 1024
#define HID 1024
#define EPI_H 512
#define PRIOR_H 5
#define PRI_N 160   // 32 ensembles * 5
#define KTOT 2048   // xf concat length

typedef unsigned long long u64;

// ---- f32x2 helpers (prior gemm) ----
__device__ __forceinline__ u64 pk2(float lo, float hi) {
    u64 r; asm("mov.b64 %0,{%1,%2};" : "=l"(r) : "f"(lo), "f"(hi)); return r;
}
__device__ __forceinline__ u64 fma2(u64 a, u64 b, u64 c) {
    u64 d; asm("fma.rn.f32x2 %0,%1,%2,%3;" : "=l"(d) : "l"(a), "l"(b), "l"(c)); return d;
}
__device__ __forceinline__ float2 unpk(u64 v) {
    float2 r; asm("mov.b64 {%0,%1},%2;" : "=f"(r.x), "=f"(r.y) : "l"(v)); return r;
}

__device__ __forceinline__ uint32_t smem_u32(const void* p) {
    uint32_t a;
    asm("{ .reg .u64 t; cvta.to.shared.u64 t, %1; cvt.u32.u64 %0, t; }" : "=r"(a) : "l"(p));
    return a;
}

// ---- Scratch (no allocation allowed) ----
__device__ float g_H[B_DIM * EPI_H];
__device__ float g_P1[B_DIM * PRI_N];
__device__ float g_W1r[STATE * PRI_N];
__device__ __align__(16) __nv_bfloat16 g_Ahi[B_DIM * KTOT];   // 8 MB
__device__ __align__(16) __nv_bfloat16 g_Alo[B_DIM * KTOT];   // 8 MB
__device__ __align__(16) __nv_bfloat16 g_Bhi[EPI_H * KTOT];   // 2 MB, [n][k]
__device__ __align__(16) __nv_bfloat16 g_Blo[EPI_H * KTOT];   // 2 MB

// ---------------------------------------------------------------------------
// Prep: split A = [x|feature] into bf16 hi/lo, row-major [2048][2048]
// ---------------------------------------------------------------------------
__global__ __launch_bounds__(256) void convert_split_A(
    const float* __restrict__ X, const float* __restrict__ F) {
    int i4 = blockIdx.x * 256 + threadIdx.x;   // 2048*2048/4 float4 groups
    int row = i4 >> 9;
    int c4 = i4 & 511;
    const float* src = (c4 < 256) ? (X + row * 1024 + c4 * 4)
                                  : (F + row * 1024 + (c4 - 256) * 4);
    float4 v = *(const float4*)src;
    __nv_bfloat16 h0 = __float2bfloat16_rn(v.x), h1 = __float2bfloat16_rn(v.y);
    __nv_bfloat16 h2 = __float2bfloat16_rn(v.z), h3 = __float2bfloat16_rn(v.w);
    __nv_bfloat16 l0 = __float2bfloat16_rn(v.x - __bfloat162float(h0));
    __nv_bfloat16 l1 = __float2bfloat16_rn(v.y - __bfloat162float(h1));
    __nv_bfloat16 l2 = __float2bfloat16_rn(v.z - __bfloat162float(h2));
    __nv_bfloat16 l3 = __float2bfloat16_rn(v.w - __bfloat162float(h3));
    __nv_bfloat162 ph0 = __halves2bfloat162(h0, h1), ph1 = __halves2bfloat162(h2, h3);
    __nv_bfloat162 pl0 = __halves2bfloat162(l0, l1), pl1 = __halves2bfloat162(l2, l3);
    uint2 uh; uh.x = *(uint32_t*)&ph0; uh.y = *(uint32_t*)&ph1;
    uint2 ul; ul.x = *(uint32_t*)&pl0; ul.y = *(uint32_t*)&pl1;
    size_t off = (size_t)row * KTOT + c4 * 4;
    *(uint2*)(g_Ahi + off) = uh;
    *(uint2*)(g_Alo + off) = ul;
}

// ---------------------------------------------------------------------------
// Prep: transpose+split W[0:2048][512] -> Bhi/Blo [512][2048]
// ---------------------------------------------------------------------------
__global__ __launch_bounds__(256) void transpose_split_W(const float* __restrict__ W) {
    __shared__ float t[32][33];
    int kt = blockIdx.x;   // 64
    int nt = blockIdx.y;   // 16
    int tx = threadIdx.x;  // 32
    int ty = threadIdx.y;  // 8
#pragma unroll
    for (int i = 0; i < 4; i++)
        t[ty * 4 + i][tx] = W[(size_t)(kt * 32 + ty * 4 + i) * EPI_H + nt * 32 + tx];
    __syncthreads();
#pragma unroll
    for (int i = 0; i < 4; i++) {
        int n = nt * 32 + ty * 4 + i;
        int k = kt * 32 + tx;
        float v = t[tx][ty * 4 + i];
        __nv_bfloat16 h = __float2bfloat16_rn(v);
        __nv_bfloat16 l = __float2bfloat16_rn(v - __bfloat162float(h));
        g_Bhi[(size_t)n * KTOT + k] = h;
        g_Blo[(size_t)n * KTOT + k] = l;
    }
}

// ---------------------------------------------------------------------------
// Repack Wp1[32][1024][5] -> W1r[1024][160]
// ---------------------------------------------------------------------------
__global__ void repack_wp1(const float* __restrict__ Wp1) {
    int idx = blockIdx.x * 256 + threadIdx.x;
    if (idx < STATE * PRI_N) {
        int k = idx / PRI_N;
        int c = idx - k * PRI_N;
        int e = c / PRIOR_H;
        int h = c - e * PRIOR_H;
        g_W1r[idx] = Wp1[e * (STATE * PRIOR_H) + k * PRIOR_H + h];
    }
}

// ---------------------------------------------------------------------------
// Tensor-core GEMM via mma.sync (bf16, 3-pass hi/lo split):
//   g_H[2048][512] = Ahi*Bhi^T + Ahi*Blo^T + Alo*Bhi^T + bias
// BM=128 BN=64 BK=32, 256 threads (8 warps, warp tile 32x32), double buffer.
// ---------------------------------------------------------------------------
#define GM_BM 128
#define GM_BN 64
#define GM_BK 32
#define NKB (KTOT / GM_BK)    // 64
// per-buffer smem layout (bytes): Ahi 8192 | Alo 8192 | Bhi 4096 | Blo 4096
#define SM_AHI 0
#define SM_ALO 8192
#define SM_BHI 16384
#define SM_BLO 20480
#define BUF_STRIDE 24576      // 24 KB, x2 = 48 KB

__device__ __forceinline__ void sts16(uint32_t base, int r, int c, uint4 v) {
    uint32_t addr = base + r * 64 + ((c ^ ((r >> 1) & 3)) * 16);
    asm volatile("st.shared.v4.b32 [%0], {%1,%2,%3,%4};"
        :: "r"(addr), "r"(v.x), "r"(v.y), "r"(v.z), "r"(v.w));
}
__device__ __forceinline__ void ldmx4(uint32_t addr, uint32_t* r) {
    asm volatile("ldmatrix.sync.aligned.m8n8.x4.shared.b16 {%0,%1,%2,%3}, [%4];"
        : "=r"(r[0]), "=r"(r[1]), "=r"(r[2]), "=r"(r[3]) : "r"(addr));
}
__device__ __forceinline__ void mma16816(float* c, const uint32_t* a,
                                         uint32_t b0, uint32_t b1) {
    asm volatile("mma.sync.aligned.m16n8k16.row.col.f32.bf16.bf16.f32 "
        "{%0,%1,%2,%3},{%4,%5,%6,%7},{%8,%9},{%0,%1,%2,%3};"
        : "+f"(c[0]), "+f"(c[1]), "+f"(c[2]), "+f"(c[3])
        : "r"(a[0]), "r"(a[1]), "r"(a[2]), "r"(a[3]), "r"(b0), "r"(b1));
}

__global__ __launch_bounds__(256, 1) void gemm_mma(const float* __restrict__ bias) {
    extern __shared__ char smem_raw[];
    const uint32_t sb = smem_u32(smem_raw);

    const int tid = threadIdx.x;
    const int lane = tid & 31;
    const int wid = tid >> 5;
    const int wm = wid & 3;        // 4 m-warps x 32 rows
    const int wn = wid >> 2;       // 2 n-warps x 32 cols
    const int row0 = blockIdx.y * GM_BM;
    const int col0 = blockIdx.x * GM_BN;

    // loader chunk coords (chunk = 16B = 8 bf16)
    const int a_r0 = tid >> 2,        a_c0 = tid & 3;        // ch = tid
    const int a_r1 = (tid + 256) >> 2, a_c1 = tid & 3;       // ch = tid+256
    const int b_r  = tid >> 2,        b_c  = tid & 3;        // 64 rows only for tid<256 ✓

    float acc[2][4][4];
#pragma unroll
    for (int mi = 0; mi < 2; mi++)
#pragma unroll
        for (int nf = 0; nf < 4; nf++)
#pragma unroll
            for (int q = 0; q < 4; q++) acc[mi][nf][q] = 0.f;

    // ---- prefetch kb=0 into buf 0 ----
    {
        const __nv_bfloat16* pAh = g_Ahi + (row0 + a_r0) * KTOT + a_c0 * 8;
        const __nv_bfloat16* pAh2 = g_Ahi + (row0 + a_r1) * KTOT + a_c1 * 8;
        const __nv_bfloat16* pAl = g_Alo + (row0 + a_r0) * KTOT + a_c0 * 8;
        const __nv_bfloat16* pAl2 = g_Alo + (row0 + a_r1) * KTOT + a_c1 * 8;
        const __nv_bfloat16* pBh = g_Bhi + (col0 + b_r) * KTOT + b_c * 8;
        const __nv_bfloat16* pBl = g_Blo + (col0 + b_r) * KTOT + b_c * 8;
        sts16(sb + SM_AHI, a_r0, a_c0, *(const uint4*)pAh);
        sts16(sb + SM_AHI, a_r1, a_c1, *(const uint4*)pAh2);
        sts16(sb + SM_ALO, a_r0, a_c0, *(const uint4*)pAl);
        sts16(sb + SM_ALO, a_r1, a_c1, *(const uint4*)pAl2);
        sts16(sb + SM_BHI, b_r, b_c, *(const uint4*)pBh);
        sts16(sb + SM_BLO, b_r, b_c, *(const uint4*)pBl);
    }
    __syncthreads();

    for (int kb = 0; kb < NKB; kb++) {
        const int cur = kb & 1;
        const uint32_t bufb = sb + cur * BUF_STRIDE;

        uint4 fAh0, fAh1, fAl0, fAl1, fBh, fBl;
        if (kb + 1 < NKB) {
            int ko = (kb + 1) * GM_BK;
            fAh0 = *(const uint4*)(g_Ahi + (row0 + a_r0) * KTOT + ko + a_c0 * 8);
            fAh1 = *(const uint4*)(g_Ahi + (row0 + a_r1) * KTOT + ko + a_c1 * 8);
            fAl0 = *(const uint4*)(g_Alo + (row0 + a_r0) * KTOT + ko + a_c0 * 8);
            fAl1 = *(const uint4*)(g_Alo + (row0 + a_r1) * KTOT + ko + a_c1 * 8);
            fBh  = *(const uint4*)(g_Bhi + (col0 + b_r) * KTOT + ko + b_c * 8);
            fBl  = *(const uint4*)(g_Blo + (col0 + b_r) * KTOT + ko + b_c * 8);
        }

        // ---- compute on cur buffer ----
#pragma unroll
        for (int kblk = 0; kblk < 2; kblk++) {
            uint32_t ah[2][4], al[2][4], bh[2][4], bl[2][4];
            const int lrow = lane & 15;
            const int lch = kblk * 2 + (lane >> 4);
#pragma unroll
            for (int mi = 0; mi < 2; mi++) {
                int r = wm * 32 + mi * 16 + lrow;
                uint32_t off = r * 64 + ((lch ^ ((r >> 1) & 3)) * 16);
                ldmx4(bufb + SM_AHI + off, ah[mi]);
                ldmx4(bufb + SM_ALO + off, al[mi]);
            }
#pragma unroll
            for (int nh = 0; nh < 2; nh++) {
                int r = wn * 32 + nh * 16 + lrow;
                uint32_t off = r * 64 + ((lch ^ ((r >> 1) & 3)) * 16);
                ldmx4(bufb + SM_BHI + off, bh[nh]);
                ldmx4(bufb + SM_BLO + off, bl[nh]);
            }
#pragma unroll
            for (int mi = 0; mi < 2; mi++)
#pragma unroll
                for (int nf = 0; nf < 4; nf++) {
                    int nh = nf >> 1, s = nf & 1;
                    mma16816(acc[mi][nf], ah[mi], bh[nh][s], bh[nh][s + 2]);
                    mma16816(acc[mi][nf], ah[mi], bl[nh][s], bl[nh][s + 2]);
                    mma16816(acc[mi][nf], al[mi], bh[nh][s], bh[nh][s + 2]);
                }
        }

        if (kb + 1 < NKB) {
            const uint32_t nb = sb + (cur ^ 1) * BUF_STRIDE;
            sts16(nb + SM_AHI, a_r0, a_c0, fAh0);
            sts16(nb + SM_AHI, a_r1, a_c1, fAh1);
            sts16(nb + SM_ALO, a_r0, a_c0, fAl0);
            sts16(nb + SM_ALO, a_r1, a_c1, fAl1);
            sts16(nb + SM_BHI, b_r, b_c, fBh);
            sts16(nb + SM_BLO, b_r, b_c, fBl);
        }
        __syncthreads();
    }

    // ---- epilogue: add bias, store to g_H ----
#pragma unroll
    for (int mi = 0; mi < 2; mi++)
#pragma unroll
        for (int nf = 0; nf < 4; nf++) {
            int r = row0 + wm * 32 + mi * 16 + (lane >> 2);
            int cc = col0 + wn * 32 + nf * 8 + (lane & 3) * 2;
            float2 b2 = *(const float2*)(bias + cc);
            float2 v0, v1;
            v0.x = acc[mi][nf][0] + b2.x; v0.y = acc[mi][nf][1] + b2.y;
            v1.x = acc[mi][nf][2] + b2.x; v1.y = acc[mi][nf][3] + b2.y;
            *(float2*)(g_H + r * EPI_H + cc) = v0;
            *(float2*)(g_H + (r + 8) * EPI_H + cc) = v1;
        }
}

// ---------------------------------------------------------------------------
// Prior GEMM: g_P1[2048][160] = relu(x @ g_W1r + bp1)   (f32x2)
// ---------------------------------------------------------------------------
#define P_BM 64
#define P_BN 32
#define P_BK 16
__global__ __launch_bounds__(128) void sgemm_prior(
    const float* __restrict__ X, const float* __restrict__ bp1) {
    __shared__ float As[2][P_BK][P_BM + 4];
    __shared__ float Bs[2][P_BK][P_BN];

    const int tid = threadIdx.x;
    const int row0 = blockIdx.y * P_BM;
    const int col0 = blockIdx.x * P_BN;

    const int ar = tid >> 2;
    const int ac4 = tid & 3;
    const int bkr = tid >> 3;
    const int bjc = tid & 7;
    const int ty = tid >> 3;
    const int tx = tid & 7;

    u64 acc2[2][4];
#pragma unroll
    for (int i = 0; i < 2; i++)
#pragma unroll
        for (int j = 0; j < 4; j++) acc2[i][j] = 0ULL;

    float4 pa0, pa1, pb;
    {
        int k = ac4 * 4;
        pa0 = *(const float4*)(X + (row0 + ar) * STATE + k);
        pa1 = *(const float4*)(X + (row0 + ar + 32) * STATE + k);
        pb  = *(const float4*)(g_W1r + bkr * PRI_N + col0 + bjc * 4);
    }
    {
        As[0][ac4 * 4 + 0][ar] = pa0.x; As[0][ac4 * 4 + 1][ar] = pa0.y;
        As[0][ac4 * 4 + 2][ar] = pa0.z; As[0][ac4 * 4 + 3][ar] = pa0.w;
        As[0][ac4 * 4 + 0][ar + 32] = pa1.x; As[0][ac4 * 4 + 1][ar + 32] = pa1.y;
        As[0][ac4 * 4 + 2][ar + 32] = pa1.z; As[0][ac4 * 4 + 3][ar + 32] = pa1.w;
        *(float4*)&Bs[0][bkr][bjc * 4] = pb;
    }
    __syncthreads();

    const int NT = STATE / P_BK;
    int buf = 0;
    for (int kt = 0; kt < NT; kt++) {
        if (kt + 1 < NT) {
            int kg = (kt + 1) * P_BK + ac4 * 4;
            pa0 = *(const float4*)(X + (row0 + ar) * STATE + kg);
            pa1 = *(const float4*)(X + (row0 + ar + 32) * STATE + kg);
            pb  = *(const float4*)(g_W1r + ((kt + 1) * P_BK + bkr) * PRI_N + col0 + bjc * 4);
        }
#pragma unroll
        for (int kk = 0; kk < P_BK; kk++) {
            ulonglong2 aa = *(const ulonglong2*)&As[buf][kk][ty * 4];
            float4 rb = *(const float4*)&Bs[buf][kk][tx * 4];
            u64 a2[2] = {aa.x, aa.y};
            u64 bd[4];
            bd[0] = pk2(rb.x, rb.x); bd[1] = pk2(rb.y, rb.y);
            bd[2] = pk2(rb.z, rb.z); bd[3] = pk2(rb.w, rb.w);
#pragma unroll
            for (int i = 0; i < 2; i++)
#pragma unroll
                for (int j = 0; j < 4; j++)
                    acc2[i][j] = fma2(a2[i], bd[j], acc2[i][j]);
        }
        if (kt + 1 < NT) {
            int nb = buf ^ 1;
            As[nb][ac4 * 4 + 0][ar] = pa0.x; As[nb][ac4 * 4 + 1][ar] = pa0.y;
            As[nb][ac4 * 4 + 2][ar] = pa0.z; As[nb][ac4 * 4 + 3][ar] = pa0.w;
            As[nb][ac4 * 4 + 0][ar + 32] = pa1.x; As[nb][ac4 * 4 + 1][ar + 32] = pa1.y;
            As[nb][ac4 * 4 + 2][ar + 32] = pa1.z; As[nb][ac4 * 4 + 3][ar + 32] = pa1.w;
            *(float4*)&Bs[nb][bkr][bjc * 4] = pb;
        }
        __syncthreads();
        buf ^= 1;
    }

    float4 bv = *(const float4*)(bp1 + col0 + tx * 4);
#pragma unroll
    for (int i2 = 0; i2 < 2; i2++) {
        float2 u0 = unpk(acc2[i2][0]), u1 = unpk(acc2[i2][1]);
        float2 u2 = unpk(acc2[i2][2]), u3 = unpk(acc2[i2][3]);
        int r = row0 + ty * 4 + 2 * i2;
        float4 olo, ohi;
        olo.x = fmaxf(u0.x + bv.x, 0.f); olo.y = fmaxf(u1.x + bv.y, 0.f);
        olo.z = fmaxf(u2.x + bv.z, 0.f); olo.w = fmaxf(u3.x + bv.w, 0.f);
        ohi.x = fmaxf(u0.y + bv.x, 0.f); ohi.y = fmaxf(u1.y + bv.y, 0.f);
        ohi.z = fmaxf(u2.y + bv.z, 0.f); ohi.w = fmaxf(u3.y + bv.w, 0.f);
        *(float4*)(g_P1 + r * PRI_N + col0 + tx * 4) = olo;
        *(float4*)(g_P1 + (r + 1) * PRI_N + col0 + tx * 4) = ohi;
    }
}

// ---------------------------------------------------------------------------
// Fused epilogue (R2 form, known 52.3us)
// ---------------------------------------------------------------------------
__global__ __launch_bounds__(512, 1) void epilogue_kernel(
    const float* __restrict__ Z, const float* __restrict__ Wep1,
    const float* __restrict__ Wep2, const float* __restrict__ bep2,
    const float* __restrict__ Wp2, const float* __restrict__ bp2,
    const float* __restrict__ Wp3, const float* __restrict__ bp3,
    float* __restrict__ out) {
    __shared__ __align__(16) float sZ[N_Z * NOISE];
    __shared__ float sP[NOISE];
    __shared__ float sRed[16][N_Z];

    const int tid = threadIdx.x;
    const int j = tid;
    const int lane = tid & 31;
    const int warp = tid >> 5;
    const int b0 = blockIdx.x * 8;

    float w1z[NOISE];
    float w2t[NOISE];
#pragma unroll
    for (int k = 0; k < NOISE; k++)
        w1z[k] = Wep1[(2048 + k) * EPI_H + j];
#pragma unroll
    for (int k4 = 0; k4 < NOISE / 4; k4++) {
        float4 v = *(const float4*)(Wep2 + j * NOISE + k4 * 4);
        w2t[k4 * 4 + 0] = v.x; w2t[k4 * 4 + 1] = v.y;
        w2t[k4 * 4 + 2] = v.z; w2t[k4 * 4 + 3] = v.w;
    }

    for (int bi = 0; bi < 8; bi++) {
        const int b = b0 + bi;
        const float Hj = g_H[b * EPI_H + j];

        if (tid >= 256) {
            int t = tid - 256;
            sZ[t] = Z[b * (N_Z * NOISE) + t];
        } else if (tid < 32) {
            int e = tid;
            const float* p1 = g_P1 + b * PRI_N + e * PRIOR_H;
            float h1[PRIOR_H];
#pragma unroll
            for (int h = 0; h < PRIOR_H; h++) h1[h] = p1[h];
            float h2[PRIOR_H];
#pragma unroll
            for (int g = 0; g < PRIOR_H; g++) {
                float s = bp2[e * PRIOR_H + g];
#pragma unroll
                for (int h = 0; h < PRIOR_H; h++)
                    s = fmaf(h1[h], Wp2[e * 25 + h * PRIOR_H + g], s);
                h2[g] = fmaxf(s, 0.f);
            }
            float p = bp3[e];
#pragma unroll
            for (int g = 0; g < PRIOR_H; g++)
                p = fmaf(h2[g], Wp3[e * PRIOR_H + g], p);
            sP[e] = p + bep2[e];
        }
        __syncthreads();

        float part[N_Z];
#pragma unroll
        for (int n = 0; n < N_Z; n++) {
            float hz = 0.f, wz = 0.f;
            const float4* z4 = (const float4*)(sZ + n * NOISE);
#pragma unroll
            for (int k4 = 0; k4 < NOISE / 4; k4++) {
                float4 zv = z4[k4];
                int k = k4 * 4;
                hz = fmaf(zv.x, w1z[k + 0], hz); wz = fmaf(zv.x, w2t[k + 0], wz);
                hz = fmaf(zv.y, w1z[k + 1], hz); wz = fmaf(zv.y, w2t[k + 1], wz);
                hz = fmaf(zv.z, w1z[k + 2], hz); wz = fmaf(zv.z, w2t[k + 2], wz);
                hz = fmaf(zv.w, w1z[k + 3], hz); wz = fmaf(zv.w, w2t[k + 3], wz);
            }
            float h = fmaxf(Hj + hz, 0.f);
            part[n] = h * wz;
        }

#pragma unroll
        for (int n = 0; n < N_Z; n++) {
            float v = part[n];
            v += __shfl_xor_sync(0xffffffffu, v, 16);
            v += __shfl_xor_sync(0xffffffffu, v, 8);
            v += __shfl_xor_sync(0xffffffffu, v, 4);
            v += __shfl_xor_sync(0xffffffffu, v, 2);
            v += __shfl_xor_sync(0xffffffffu, v, 1);
            if (lane == 0) sRed[warp][n] = v;
        }
        __syncthreads();

        if (tid < N_Z) {
            float s = 0.f;
#pragma unroll
            for (int w = 0; w < 16; w++) s += sRed[w][tid];
            const float* zn = sZ + tid * NOISE;
#pragma unroll
            for (int e = 0; e < NOISE; e++) s = fmaf(sP[e], zn[e], s);
            out[b * N_Z + tid] = s;
        }
        __syncthreads();
    }
}

// ---------------------------------------------------------------------------
extern "C" void kernel_launch(void* const* d_in, const int* in_sizes, int n_in,
                              void* d_out, int out_size) {
    const float* x    = (const float*)d_in[0];
    const float* feat = (const float*)d_in[1];
    const float* z    = (const float*)d_in[2];
    const float* Wep1 = (const float*)d_in[3];
    const float* bep1 = (const float*)d_in[4];
    const float* Wep2 = (const float*)d_in[5];
    const float* bep2 = (const float*)d_in[6];
    const float* Wp1  = (const float*)d_in[7];
    const float* bp1  = (const float*)d_in[8];
    const float* Wp2  = (const float*)d_in[9];
    const float* bp2  = (const float*)d_in[10];
    const float* Wp3  = (const float*)d_in[11];
    const float* bp3  = (const float*)d_in[12];
    float* out = (float*)d_out;

    convert_split_A<<<(B_DIM * KTOT / 4) / 256, 256>>>(x, feat);
    transpose_split_W<<<dim3(64, 16), dim3(32, 8)>>>(Wep1);
    repack_wp1<<<(STATE * PRI_N + 255) / 256, 256>>>(Wp1);
    gemm_mma<<<dim3(EPI_H / GM_BN, B_DIM / GM_BM), 256, 2 * BUF_STRIDE>>>(bep1);
    sgemm_prior<<<dim3(PRI_N / P_BN, B_DIM / P_BM), 128>>>(x, bp1);
    epilogue_kernel<<<B_DIM / 8, 512>>>(z, Wep1, Wep2, bep2, Wp2, bp2, Wp3, bp3, out);
}